// round 1
// baseline (speedup 1.0000x reference)
#include <cuda_runtime.h>
#include <math.h>

#define T_STEPS 16
#define BATCH   64
#define DG      512
#define DH      1024
#define DOUT    512
#define S_STEPS 3
#define LAMBDA  0.95f
#define ETA     0.5f

// ---------------- device scratch (no allocation allowed) ----------------
__device__ float g_h[BATCH * DH];
__device__ float g_parts[3][BATCH * DH];        // k-split GEMM partials
__device__ float g_hist[T_STEPS - 1][BATCH * DH];
__device__ float g_hp[2][BATCH * DOUT];         // head GEMM partials
__device__ float g_lossb[BATCH];
__device__ float g_accb[BATCH];

// ---------------- f32x2 packed-FMA helpers (Blackwell double-rate) -------
__device__ __forceinline__ unsigned long long ffma2(unsigned long long a,
                                                    unsigned long long b,
                                                    unsigned long long c) {
    unsigned long long d;
    asm("fma.rn.f32x2 %0, %1, %2, %3;" : "=l"(d) : "l"(a), "l"(b), "l"(c));
    return d;
}
__device__ __forceinline__ void upk2(unsigned long long v, float& x, float& y) {
    asm("mov.b64 {%0,%1}, %2;" : "=f"(x), "=f"(y) : "l"(v));
}

// ---------------- GEMM core: out[b][n0+n] = sum_k X[b][k0+k]*W[n0+n][k0+k]
// M=64 (all batches), N-tile=32, K=512 fixed (16 chunks of 32).
// 256 threads: thread = (mg 0..15, ng 0..15) computes 4 m-rows x 2 n-cols.
__device__ __forceinline__ void gemm_core(const float* __restrict__ X, int ldx,
                                          const float* __restrict__ W, int ldw,
                                          float* __restrict__ out, int ldo,
                                          int n0, int k0) {
    __shared__ __align__(16) float  Xs[32][66];   // [k][m], padded
    __shared__ __align__(16) float2 Ws[32][33];   // [k][n] as (w,w), padded

    const int tid = threadIdx.x;
    const int mg = tid & 15, ng = tid >> 4;
    const int r0 = mg * 4, c0 = ng * 2;
    const int lm = tid >> 5;        // load row base (m = lm + i*8, n = lm + i*8)
    const int lk = tid & 31;        // load k within chunk

    const float* Xg = X + k0 + lk;
    const float* Wg = W + (size_t)(n0 + lm) * ldw + k0 + lk;

    float xr[8], wr[4];
#pragma unroll
    for (int i = 0; i < 8; i++) xr[i] = Xg[(size_t)(lm + i * 8) * ldx];
#pragma unroll
    for (int i = 0; i < 4; i++) wr[i] = Wg[(size_t)(i * 8) * ldw];

    unsigned long long a00 = 0ull, a10 = 0ull, a01 = 0ull, a11 = 0ull;

#pragma unroll 1
    for (int ch = 0; ch < 16; ch++) {
        __syncthreads();
#pragma unroll
        for (int i = 0; i < 8; i++) Xs[lk][lm + i * 8] = xr[i];
#pragma unroll
        for (int i = 0; i < 4; i++) Ws[lk][lm + i * 8] = make_float2(wr[i], wr[i]);
        __syncthreads();
        if (ch < 15) {  // prefetch next chunk under compute
            const float* Xg2 = Xg + (ch + 1) * 32;
            const float* Wg2 = Wg + (ch + 1) * 32;
#pragma unroll
            for (int i = 0; i < 8; i++) xr[i] = Xg2[(size_t)(lm + i * 8) * ldx];
#pragma unroll
            for (int i = 0; i < 4; i++) wr[i] = Wg2[(size_t)(i * 8) * ldw];
        }
#pragma unroll
        for (int kk = 0; kk < 32; kk++) {
            unsigned long long x01 = *(const unsigned long long*)&Xs[kk][r0];
            unsigned long long x23 = *(const unsigned long long*)&Xs[kk][r0 + 2];
            unsigned long long w0  = *(const unsigned long long*)&Ws[kk][c0];
            unsigned long long w1  = *(const unsigned long long*)&Ws[kk][c0 + 1];
            a00 = ffma2(x01, w0, a00);
            a10 = ffma2(x23, w0, a10);
            a01 = ffma2(x01, w1, a01);
            a11 = ffma2(x23, w1, a11);
        }
    }

    float v0, v1;
    upk2(a00, v0, v1);
    out[(r0    ) * ldo + n0 + c0] = v0;
    out[(r0 + 1) * ldo + n0 + c0] = v1;
    upk2(a10, v0, v1);
    out[(r0 + 2) * ldo + n0 + c0] = v0;
    out[(r0 + 3) * ldo + n0 + c0] = v1;
    upk2(a01, v0, v1);
    out[(r0    ) * ldo + n0 + c0 + 1] = v0;
    out[(r0 + 1) * ldo + n0 + c0 + 1] = v1;
    upk2(a11, v0, v1);
    out[(r0 + 2) * ldo + n0 + c0 + 1] = v0;
    out[(r0 + 3) * ldo + n0 + c0 + 1] = v1;
}

__global__ void __launch_bounds__(256) gemm_step_kernel(
    const float* __restrict__ z_seq, const float* __restrict__ W_h,
    const float* __restrict__ W_g, int t) {
    const int y = blockIdx.y, n0 = blockIdx.x * 32;
    if (y == 0)
        gemm_core(g_h, DH, W_h, DH, g_parts[0], DH, n0, 0);
    else if (y == 1)
        gemm_core(g_h, DH, W_h, DH, g_parts[1], DH, n0, 512);
    else
        gemm_core(z_seq + (size_t)t * BATCH * DG, DG, W_g, DG, g_parts[2], DH, n0, 0);
}

__global__ void __launch_bounds__(256) head_gemm_kernel(const float* __restrict__ head_W) {
    const int y = blockIdx.y, n0 = blockIdx.x * 32;
    gemm_core(g_h, DH, head_W, DH, g_hp[y], DOUT, n0, y * 512);
}

// ---------------- block reduction: NV values, two-stage shfl + smem ------
template <int NV>
__device__ __forceinline__ void block_reduce_bc(const float* vals, float* bc,
                                                float (*red)[17]) {
    const int lane = threadIdx.x & 31, warp = threadIdx.x >> 5;
    const int nw = blockDim.x >> 5;
#pragma unroll
    for (int v = 0; v < NV; v++) {
        float x = vals[v];
#pragma unroll
        for (int o = 16; o > 0; o >>= 1) x += __shfl_down_sync(0xffffffffu, x, o);
        if (lane == 0) red[warp][v] = x;
    }
    __syncthreads();
    if (warp < NV) {
        float x = (lane < nw) ? red[lane][warp] : 0.f;
#pragma unroll
        for (int o = 16; o > 0; o >>= 1) x += __shfl_down_sync(0xffffffffu, x, o);
        if (lane == 0) bc[warp] = x;
    }
    __syncthreads();
}

// 16 simultaneous history dot-products (partials computed in-place, no p[] array)
__device__ __forceinline__ void block_reduce_dots(const float* hv, float h, float* bc,
                                                  float (*red)[17]) {
    const int lane = threadIdx.x & 31, warp = threadIdx.x >> 5;
#pragma unroll
    for (int v = 0; v < 15; v++) {
        float x = hv[v] * h;
#pragma unroll
        for (int o = 16; o > 0; o >>= 1) x += __shfl_down_sync(0xffffffffu, x, o);
        if (lane == 0) red[warp][v] = x;
    }
    __syncthreads();
    if (warp < 15) {
        float x = red[lane][warp];
#pragma unroll
        for (int o = 16; o > 0; o >>= 1) x += __shfl_down_sync(0xffffffffu, x, o);
        if (lane == 0) bc[warp] = x;
    }
    __syncthreads();
}

// ---------------- fused refinement kernel (one block per batch element) --
__global__ void __launch_bounds__(1024) refine_kernel(
    const float* __restrict__ b_h, const float* __restrict__ gamma_p,
    const float* __restrict__ beta_p, const float* __restrict__ alpha_p,
    int t, int is_last) {
    const int b = blockIdx.x, i = threadIdx.x;
    __shared__ float red[32][17];
    __shared__ float bc[16];
    __shared__ float wd[16];   // decay weights eta*lambda^(t-1-tau)

    const float g  = gamma_p[i];
    const float be = beta_p[i];
    float hb = g_parts[0][b * DH + i] + g_parts[1][b * DH + i] +
               g_parts[2][b * DH + i] + b_h[i];

    // load history vectors into registers
    float hv[15];
#pragma unroll
    for (int tau = 0; tau < 15; tau++)
        hv[tau] = (tau < t) ? g_hist[tau][b * DH + i] : 0.f;

    if (i < 16) wd[i] = (i < t) ? ETA * powf(LAMBDA, (float)(t - 1 - i)) : 0.f;

    // gating exponent k from alpha
    const float alpha = *alpha_p;
    const float spp = fmaxf(alpha, 0.f) + log1pf(expf(-fabsf(alpha)));
    const float spn = fmaxf(-alpha, 0.f) + log1pf(expf(-fabsf(alpha)));
    const float kco = (alpha >= 0.f) ? (1.f + spp) : (1.f / (1.f + spn));

    // initial LN + relu
    float h;
    {
        float v[2] = {hb, hb * hb};
        block_reduce_bc<2>(v, bc, red);
        float mu  = bc[0] * (1.f / DH);
        float var = bc[1] * (1.f / DH) - mu * mu;
        h = fmaxf((hb - mu) * rsqrtf(var + 1e-5f) * g + be, 0.f);
    }

    for (int s = 0; s < S_STEPS; s++) {
        block_reduce_dots(hv, h, bc, red);  // bc[tau] = h_tau . h
        float Ah = 0.f;
#pragma unroll
        for (int tau = 0; tau < 15; tau++) Ah += (wd[tau] * bc[tau]) * hv[tau];

        float hn;
        if (!is_last) {
            float v3[3] = {h * Ah, h * h, Ah * Ah};
            block_reduce_bc<3>(v3, bc, red);
            float dot = bc[0];
            float n1 = sqrtf(bc[1]) + 1e-6f;
            float n2 = sqrtf(bc[2]) + 1e-6f;
            float R  = dot / (n1 * n2 + 1e-6f);
            float Rp = fminf(fmaxf(R, 0.f), 1.f);
            float a  = 1.f - powf(1.f - Rp, kco);
            hn = (1.f - a * a) * hb + a * Ah;
        } else {
            hn = hb + Ah;
        }
        float v2[2] = {hn, hn * hn};
        block_reduce_bc<2>(v2, bc, red);
        float mu  = bc[0] * (1.f / DH);
        float var = bc[1] * (1.f / DH) - mu * mu;
        h = fmaxf((hn - mu) * rsqrtf(var + 1e-5f) * g + be, 0.f);
    }

    g_h[b * DH + i] = h;
    if (!is_last) g_hist[t][b * DH + i] = h;   // Hebbian update == append to history
}

// ---------------- head loss / acc --------------------------------------
__global__ void __launch_bounds__(512) head_loss_kernel(
    const float* __restrict__ clean, const float* __restrict__ head_b) {
    const int b = blockIdx.x, o = threadIdx.x;
    __shared__ float red[32][17];
    __shared__ float bc[16];
    float pred = g_hp[0][b * DOUT + o] + g_hp[1][b * DOUT + o] + head_b[o];
    float c = clean[b * DOUT + o];
    float d = pred - c;
    float v[4] = {pred * c, pred * pred, c * c, d * d};
    block_reduce_bc<4>(v, bc, red);
    if (o == 0) {
        g_lossb[b] = bc[3] / (bc[2] + 1e-6f);
        g_accb[b]  = bc[0] / ((sqrtf(bc[1]) + 1e-6f) * (sqrtf(bc[2]) + 1e-6f));
    }
}

__global__ void finalize_kernel(float* __restrict__ out) {
    const int lane = threadIdx.x;  // 32 threads
    float l = g_lossb[lane] + g_lossb[lane + 32];
    float a = g_accb[lane] + g_accb[lane + 32];
#pragma unroll
    for (int o = 16; o > 0; o >>= 1) {
        l += __shfl_down_sync(0xffffffffu, l, o);
        a += __shfl_down_sync(0xffffffffu, a, o);
    }
    if (lane == 0) {
        out[0] = l * (1.f / BATCH);
        out[1] = a * (1.f / BATCH);
    }
}

__global__ void zero_h_kernel() { g_h[blockIdx.x * 1024 + threadIdx.x] = 0.f; }

// ---------------- launch -------------------------------------------------
extern "C" void kernel_launch(void* const* d_in, const int* in_sizes, int n_in,
                              void* d_out, int out_size) {
    const float* z_seq  = (const float*)d_in[0];
    const float* clean  = (const float*)d_in[1];
    const float* W_h    = (const float*)d_in[2];
    const float* W_g    = (const float*)d_in[3];
    const float* b_h    = (const float*)d_in[4];
    const float* ln_g   = (const float*)d_in[5];
    const float* ln_b   = (const float*)d_in[6];
    const float* alpha  = (const float*)d_in[7];
    const float* head_W = (const float*)d_in[8];
    const float* head_b = (const float*)d_in[9];
    float* out = (float*)d_out;

    zero_h_kernel<<<64, 1024>>>();
    for (int t = 0; t < T_STEPS; t++) {
        gemm_step_kernel<<<dim3(32, 3), 256>>>(z_seq, W_h, W_g, t);
        refine_kernel<<<64, 1024>>>(b_h, ln_g, ln_b, alpha, t, t == T_STEPS - 1 ? 1 : 0);
    }
    head_gemm_kernel<<<dim3(16, 2), 256>>>(head_W);
    head_loss_kernel<<<64, 512>>>(clean, head_b);
    finalize_kernel<<<1, 32>>>(out);
}

// round 2
// speedup vs baseline: 1.1776x; 1.1776x over previous
#include <cuda_runtime.h>
#include <math.h>

#define T_STEPS 16
#define BATCH   64
#define DG      512
#define DH      1024
#define DOUT    512
#define S_STEPS 3
#define LAMBDA  0.95f
#define ETA     0.5f

#define KSPLIT_H 8      // W_h step GEMM k-splits (k=128 each)
#define KSPLIT_O 8      // head GEMM k-splits

// ---------------- device scratch (no allocation allowed) ----------------
__device__ float g_h[BATCH * DH];
__device__ float g_parts[KSPLIT_H][BATCH * DH];     // W_h k-split partials
__device__ float g_zwg[T_STEPS * BATCH * DH];       // precomputed z @ W_g^T (all t)
__device__ float g_hist[T_STEPS - 1][BATCH * DH];   // h history (rank-15 fast weight)
__device__ float g_hp[KSPLIT_O][BATCH * DOUT];      // head GEMM partials
__device__ float g_lossb[BATCH];
__device__ float g_accb[BATCH];

// ---------------- f32x2 packed-FMA helpers (Blackwell double-rate) -------
__device__ __forceinline__ unsigned long long ffma2(unsigned long long a,
                                                    unsigned long long b,
                                                    unsigned long long c) {
    unsigned long long d;
    asm("fma.rn.f32x2 %0, %1, %2, %3;" : "=l"(d) : "l"(a), "l"(b), "l"(c));
    return d;
}
__device__ __forceinline__ void upk2(unsigned long long v, float& x, float& y) {
    asm("mov.b64 {%0,%1}, %2;" : "=f"(x), "=f"(y) : "l"(v));
}

// ---------------- GEMM core: 64m x 64n block tile, K chunked by 16 ------
// out[m0+m][n0+n] (+)= sum_{k in [k0, k0+16*nch)} X[m0+m][k] * W[n0+n][k]
// 256 threads; thread (mg 0..7, ng 0..31) owns 8 m-rows x 2 n-cols.
// Per kk: 3 LDS.128 feed 8 FFMA2 (ratio 2.67 -> fma-bound).
#define PADX 68   // floats per Xs row (272B, 16B aligned)
#define PADW 66   // float2 per Ws row (528B, 16B aligned)

__device__ __forceinline__ void gemm64(
    const float* __restrict__ X, int ldx,
    const float* __restrict__ W, int ldw,
    float* __restrict__ out, int ldo,
    int m0, int n0, int k0, int nch)
{
    __shared__ __align__(16) float  Xs[16][PADX];
    __shared__ __align__(16) float2 Ws[16][PADW];

    const int tid = threadIdx.x;
    const int mg = tid & 7, ng = tid >> 3;      // compute mapping
    const int q  = tid & 3, rr = tid >> 2;      // load mapping (rr 0..63)

    const float4* Xg = (const float4*)(X + (size_t)(m0 + rr) * ldx + k0) + q;
    const float4* Wg = (const float4*)(W + (size_t)(n0 + rr) * ldw + k0) + q;

    float4 xr = *Xg;
    float4 wr = *Wg;

    unsigned long long acc[4][2];
#pragma unroll
    for (int r = 0; r < 4; r++)
#pragma unroll
        for (int c = 0; c < 2; c++) acc[r][c] = 0ull;

#pragma unroll 1
    for (int ch = 0; ch < nch; ch++) {
        __syncthreads();
        Xs[q * 4 + 0][rr] = xr.x;
        Xs[q * 4 + 1][rr] = xr.y;
        Xs[q * 4 + 2][rr] = xr.z;
        Xs[q * 4 + 3][rr] = xr.w;
        Ws[q * 4 + 0][rr] = make_float2(wr.x, wr.x);
        Ws[q * 4 + 1][rr] = make_float2(wr.y, wr.y);
        Ws[q * 4 + 2][rr] = make_float2(wr.z, wr.z);
        Ws[q * 4 + 3][rr] = make_float2(wr.w, wr.w);
        __syncthreads();
        if (ch + 1 < nch) {            // prefetch next chunk under compute
            xr = Xg[(ch + 1) * 4];
            wr = Wg[(ch + 1) * 4];
        }
#pragma unroll
        for (int kk = 0; kk < 16; kk++) {
            ulonglong2 xa = *(const ulonglong2*)&Xs[kk][mg * 8];
            ulonglong2 xb = *(const ulonglong2*)&Xs[kk][mg * 8 + 4];
            ulonglong2 wv = *(const ulonglong2*)&Ws[kk][ng * 2];
            acc[0][0] = ffma2(xa.x, wv.x, acc[0][0]);
            acc[1][0] = ffma2(xa.y, wv.x, acc[1][0]);
            acc[2][0] = ffma2(xb.x, wv.x, acc[2][0]);
            acc[3][0] = ffma2(xb.y, wv.x, acc[3][0]);
            acc[0][1] = ffma2(xa.x, wv.y, acc[0][1]);
            acc[1][1] = ffma2(xa.y, wv.y, acc[1][1]);
            acc[2][1] = ffma2(xb.x, wv.y, acc[2][1]);
            acc[3][1] = ffma2(xb.y, wv.y, acc[3][1]);
        }
    }

#pragma unroll
    for (int r = 0; r < 4; r++)
#pragma unroll
        for (int c = 0; c < 2; c++) {
            float v0, v1;
            upk2(acc[r][c], v0, v1);
            const int m = m0 + mg * 8 + r * 2;
            const int n = n0 + ng * 2 + c;
            out[(size_t)m * ldo + n]       = v0;
            out[(size_t)(m + 1) * ldo + n] = v1;
        }
}

// -------- one-time: zwg[t*64+b][n] = z_seq[t][b] . W_g[n]  (1024x1024x512)
__global__ void __launch_bounds__(256) zwg_kernel(
    const float* __restrict__ z_seq, const float* __restrict__ W_g) {
    gemm64(z_seq, DG, W_g, DG, g_zwg, DH, blockIdx.y * 64, blockIdx.x * 64, 0, 32);
}

// -------- per-step: g_parts[ks] = h @ W_h^T  (k-slice)
__global__ void __launch_bounds__(256) wh_step_kernel(const float* __restrict__ W_h) {
    gemm64(g_h, DH, W_h, DH, g_parts[blockIdx.y], DH,
           0, blockIdx.x * 64, blockIdx.y * 128, 8);
}

__global__ void __launch_bounds__(256) head_gemm_kernel(const float* __restrict__ head_W) {
    gemm64(g_h, DH, head_W, DH, g_hp[blockIdx.y], DOUT,
           0, blockIdx.x * 64, blockIdx.y * 128, 8);
}

// ---------------- block reduction: NV values, two-stage shfl + smem ------
template <int NV>
__device__ __forceinline__ void block_reduce_bc(const float* vals, float* bc,
                                                float (*red)[17]) {
    const int lane = threadIdx.x & 31, warp = threadIdx.x >> 5;
    const int nw = blockDim.x >> 5;
#pragma unroll
    for (int v = 0; v < NV; v++) {
        float x = vals[v];
#pragma unroll
        for (int o = 16; o > 0; o >>= 1) x += __shfl_down_sync(0xffffffffu, x, o);
        if (lane == 0) red[warp][v] = x;
    }
    __syncthreads();
    if (warp < NV) {
        float x = (lane < nw) ? red[lane][warp] : 0.f;
#pragma unroll
        for (int o = 16; o > 0; o >>= 1) x += __shfl_down_sync(0xffffffffu, x, o);
        if (lane == 0) bc[warp] = x;
    }
    __syncthreads();
}

// 15 simultaneous history dot-products
__device__ __forceinline__ void block_reduce_dots(const float* hv, float h, float* bc,
                                                  float (*red)[17]) {
    const int lane = threadIdx.x & 31, warp = threadIdx.x >> 5;
#pragma unroll
    for (int v = 0; v < 15; v++) {
        float x = hv[v] * h;
#pragma unroll
        for (int o = 16; o > 0; o >>= 1) x += __shfl_down_sync(0xffffffffu, x, o);
        if (lane == 0) red[warp][v] = x;
    }
    __syncthreads();
    if (warp < 15) {
        float x = red[lane][warp];
#pragma unroll
        for (int o = 16; o > 0; o >>= 1) x += __shfl_down_sync(0xffffffffu, x, o);
        if (lane == 0) bc[warp] = x;
    }
    __syncthreads();
}

// ---------------- fused refinement kernel (one block per batch element) --
__global__ void __launch_bounds__(1024) refine_kernel(
    const float* __restrict__ b_h, const float* __restrict__ gamma_p,
    const float* __restrict__ beta_p, const float* __restrict__ alpha_p,
    int t, int is_last) {
    const int b = blockIdx.x, i = threadIdx.x;
    __shared__ float red[32][17];
    __shared__ float bc[16];
    __shared__ float wd[16];

    const float g  = gamma_p[i];
    const float be = beta_p[i];

    float hb = b_h[i] + g_zwg[((size_t)t * BATCH + b) * DH + i];
    if (t > 0) {
#pragma unroll
        for (int s = 0; s < KSPLIT_H; s++) hb += g_parts[s][b * DH + i];
    }

    float hv[15];
#pragma unroll
    for (int tau = 0; tau < 15; tau++)
        hv[tau] = (tau < t) ? g_hist[tau][b * DH + i] : 0.f;

    if (i < 16) wd[i] = (i < t) ? ETA * powf(LAMBDA, (float)(t - 1 - i)) : 0.f;

    const float alpha = *alpha_p;
    const float spp = fmaxf(alpha, 0.f) + log1pf(expf(-fabsf(alpha)));
    const float spn = fmaxf(-alpha, 0.f) + log1pf(expf(-fabsf(alpha)));
    const float kco = (alpha >= 0.f) ? (1.f + spp) : (1.f / (1.f + spn));

    float h;
    {
        float v[2] = {hb, hb * hb};
        block_reduce_bc<2>(v, bc, red);
        float mu  = bc[0] * (1.f / DH);
        float var = bc[1] * (1.f / DH) - mu * mu;
        h = fmaxf((hb - mu) * rsqrtf(var + 1e-5f) * g + be, 0.f);
    }

    for (int s = 0; s < S_STEPS; s++) {
        block_reduce_dots(hv, h, bc, red);
        float Ah = 0.f;
#pragma unroll
        for (int tau = 0; tau < 15; tau++) Ah += (wd[tau] * bc[tau]) * hv[tau];

        float hn;
        if (!is_last) {
            float v3[3] = {h * Ah, h * h, Ah * Ah};
            block_reduce_bc<3>(v3, bc, red);
            float dot = bc[0];
            float n1 = sqrtf(bc[1]) + 1e-6f;
            float n2 = sqrtf(bc[2]) + 1e-6f;
            float R  = dot / (n1 * n2 + 1e-6f);
            float Rp = fminf(fmaxf(R, 0.f), 1.f);
            float a  = 1.f - powf(1.f - Rp, kco);
            hn = (1.f - a * a) * hb + a * Ah;
        } else {
            hn = hb + Ah;
        }
        float v2[2] = {hn, hn * hn};
        block_reduce_bc<2>(v2, bc, red);
        float mu  = bc[0] * (1.f / DH);
        float var = bc[1] * (1.f / DH) - mu * mu;
        h = fmaxf((hn - mu) * rsqrtf(var + 1e-5f) * g + be, 0.f);
    }

    g_h[b * DH + i] = h;
    if (!is_last) g_hist[t][b * DH + i] = h;
}

// ---------------- head loss / acc --------------------------------------
__global__ void __launch_bounds__(512) head_loss_kernel(
    const float* __restrict__ clean, const float* __restrict__ head_b) {
    const int b = blockIdx.x, o = threadIdx.x;
    __shared__ float red[32][17];
    __shared__ float bc[16];
    float pred = head_b[o];
#pragma unroll
    for (int s = 0; s < KSPLIT_O; s++) pred += g_hp[s][b * DOUT + o];
    float c = clean[b * DOUT + o];
    float d = pred - c;
    float v[4] = {pred * c, pred * pred, c * c, d * d};
    block_reduce_bc<4>(v, bc, red);
    if (o == 0) {
        g_lossb[b] = bc[3] / (bc[2] + 1e-6f);
        g_accb[b]  = bc[0] / ((sqrtf(bc[1]) + 1e-6f) * (sqrtf(bc[2]) + 1e-6f));
    }
}

__global__ void finalize_kernel(float* __restrict__ out) {
    const int lane = threadIdx.x;  // 32 threads
    float l = g_lossb[lane] + g_lossb[lane + 32];
    float a = g_accb[lane] + g_accb[lane + 32];
#pragma unroll
    for (int o = 16; o > 0; o >>= 1) {
        l += __shfl_down_sync(0xffffffffu, l, o);
        a += __shfl_down_sync(0xffffffffu, a, o);
    }
    if (lane == 0) {
        out[0] = l * (1.f / BATCH);
        out[1] = a * (1.f / BATCH);
    }
}

// ---------------- launch -------------------------------------------------
extern "C" void kernel_launch(void* const* d_in, const int* in_sizes, int n_in,
                              void* d_out, int out_size) {
    const float* z_seq  = (const float*)d_in[0];
    const float* clean  = (const float*)d_in[1];
    const float* W_h    = (const float*)d_in[2];
    const float* W_g    = (const float*)d_in[3];
    const float* b_h    = (const float*)d_in[4];
    const float* ln_g   = (const float*)d_in[5];
    const float* ln_b   = (const float*)d_in[6];
    const float* alpha  = (const float*)d_in[7];
    const float* head_W = (const float*)d_in[8];
    const float* head_b = (const float*)d_in[9];
    float* out = (float*)d_out;

    // all z @ W_g^T at once (h-independent, off the serial path)
    zwg_kernel<<<dim3(16, 16), 256>>>(z_seq, W_g);

    // t = 0: h is zero -> skip W_h GEMM entirely
    refine_kernel<<<64, 1024>>>(b_h, ln_g, ln_b, alpha, 0, 0);
    for (int t = 1; t < T_STEPS; t++) {
        wh_step_kernel<<<dim3(16, KSPLIT_H), 256>>>(W_h);
        refine_kernel<<<64, 1024>>>(b_h, ln_g, ln_b, alpha, t, t == T_STEPS - 1 ? 1 : 0);
    }
    head_gemm_kernel<<<dim3(8, KSPLIT_O), 256>>>(head_W);
    head_loss_kernel<<<64, 512>>>(clean, head_b);
    finalize_kernel<<<1, 32>>>(out);
}

// round 4
// speedup vs baseline: 1.4036x; 1.1918x over previous
#include <cuda_runtime.h>
#include <math.h>

#define T_STEPS 16
#define BATCH   64
#define DG      512
#define DH      1024
#define DOUT    512
#define S_STEPS 3
#define LAMBDA  0.95f
#define ETA     0.5f

#define KSPLIT_H 16
#define KSPLIT_O 16

// ---------------- device scratch ----------------
__device__ float g_h[BATCH * DH];
__device__ float g_parts[KSPLIT_H][BATCH * DH];
__device__ float g_zwg[T_STEPS * BATCH * DH];
__device__ float g_hist[T_STEPS - 1][BATCH * DH];
__device__ float g_gram[BATCH * 16 * 16];   // history Gram, per batch
__device__ float g_hsum[BATCH * 16];        // per-history-vector element sums
__device__ float g_hp[KSPLIT_O][BATCH * DOUT];
__device__ float g_lossb[BATCH];
__device__ float g_accb[BATCH];

// ---------------- f32x2 packed FMA ----------------
__device__ __forceinline__ unsigned long long ffma2(unsigned long long a,
                                                    unsigned long long b,
                                                    unsigned long long c) {
    unsigned long long d;
    asm("fma.rn.f32x2 %0, %1, %2, %3;" : "=l"(d) : "l"(a), "l"(b), "l"(c));
    return d;
}
__device__ __forceinline__ void upk2(unsigned long long v, float& x, float& y) {
    asm("mov.b64 {%0,%1}, %2;" : "=f"(x), "=f"(y) : "l"(v));
}

// ---------------- GEMM 64x64 tile ----------------
#define PADX 68
#define PADW 66

__device__ __forceinline__ void gemm64(
    const float* __restrict__ X, int ldx,
    const float* __restrict__ W, int ldw,
    float* __restrict__ out, int ldo,
    int m0, int n0, int k0, int nch)
{
    __shared__ __align__(16) float  Xs[16][PADX];
    __shared__ __align__(16) float2 Ws[16][PADW];

    const int tid = threadIdx.x;
    const int mg = tid & 7, ng = tid >> 3;
    const int q  = tid & 3, rr = tid >> 2;

    const float4* Xg = (const float4*)(X + (size_t)(m0 + rr) * ldx + k0) + q;
    const float4* Wg = (const float4*)(W + (size_t)(n0 + rr) * ldw + k0) + q;

    float4 xr = *Xg;
    float4 wr = *Wg;

    unsigned long long acc[4][2];
#pragma unroll
    for (int r = 0; r < 4; r++)
#pragma unroll
        for (int c = 0; c < 2; c++) acc[r][c] = 0ull;

#pragma unroll 1
    for (int ch = 0; ch < nch; ch++) {
        __syncthreads();
        Xs[q * 4 + 0][rr] = xr.x;
        Xs[q * 4 + 1][rr] = xr.y;
        Xs[q * 4 + 2][rr] = xr.z;
        Xs[q * 4 + 3][rr] = xr.w;
        Ws[q * 4 + 0][rr] = make_float2(wr.x, wr.x);
        Ws[q * 4 + 1][rr] = make_float2(wr.y, wr.y);
        Ws[q * 4 + 2][rr] = make_float2(wr.z, wr.z);
        Ws[q * 4 + 3][rr] = make_float2(wr.w, wr.w);
        __syncthreads();
        if (ch + 1 < nch) {
            xr = Xg[(ch + 1) * 4];
            wr = Wg[(ch + 1) * 4];
        }
#pragma unroll
        for (int kk = 0; kk < 16; kk++) {
            ulonglong2 xa = *(const ulonglong2*)&Xs[kk][mg * 8];
            ulonglong2 xb = *(const ulonglong2*)&Xs[kk][mg * 8 + 4];
            ulonglong2 wv = *(const ulonglong2*)&Ws[kk][ng * 2];
            acc[0][0] = ffma2(xa.x, wv.x, acc[0][0]);
            acc[1][0] = ffma2(xa.y, wv.x, acc[1][0]);
            acc[2][0] = ffma2(xb.x, wv.x, acc[2][0]);
            acc[3][0] = ffma2(xb.y, wv.x, acc[3][0]);
            acc[0][1] = ffma2(xa.x, wv.y, acc[0][1]);
            acc[1][1] = ffma2(xa.y, wv.y, acc[1][1]);
            acc[2][1] = ffma2(xb.x, wv.y, acc[2][1]);
            acc[3][1] = ffma2(xb.y, wv.y, acc[3][1]);
        }
    }

#pragma unroll
    for (int r = 0; r < 4; r++)
#pragma unroll
        for (int c = 0; c < 2; c++) {
            float v0, v1;
            upk2(acc[r][c], v0, v1);
            const int m = m0 + mg * 8 + r * 2;
            const int n = n0 + ng * 2 + c;
            out[(size_t)m * ldo + n]       = v0;
            out[(size_t)(m + 1) * ldo + n] = v1;
        }
}

__global__ void __launch_bounds__(256) zwg_kernel(
    const float* __restrict__ z_seq, const float* __restrict__ W_g) {
    gemm64(z_seq, DG, W_g, DG, g_zwg, DH, blockIdx.y * 64, blockIdx.x * 64, 0, 32);
}

__global__ void __launch_bounds__(256) wh_step_kernel(const float* __restrict__ W_h) {
    gemm64(g_h, DH, W_h, DH, g_parts[blockIdx.y], DH,
           0, blockIdx.x * 64, blockIdx.y * 64, 4);
}

__global__ void __launch_bounds__(256) head_gemm_kernel(const float* __restrict__ head_W) {
    gemm64(g_h, DH, head_W, DH, g_hp[blockIdx.y], DOUT,
           0, blockIdx.x * 64, blockIdx.y * 64, 4);
}

// ---------------- 512-thread multi-value block reduction ----------------
template <int NV>
__device__ __forceinline__ void reduce512(const float* v, float* bc, float (*red)[18]) {
    const int lane = threadIdx.x & 31, warp = threadIdx.x >> 5;
#pragma unroll
    for (int x = 0; x < NV; x++) {
        float s = v[x];
#pragma unroll
        for (int o = 16; o > 0; o >>= 1) s += __shfl_down_sync(0xffffffffu, s, o);
        if (lane == 0) red[warp][x] = s;
    }
    __syncthreads();
    for (int x = warp; x < NV; x += 16) {
        float s = (lane < 16) ? red[lane][x] : 0.f;
#pragma unroll
        for (int o = 8; o > 0; o >>= 1) s += __shfl_down_sync(0xffffffffu, s, o);
        if (lane == 0) bc[x] = s;
    }
    __syncthreads();
}

// ---------------- refinement: one block (512 thr) per batch element -----
// All gating scalars derived from d[tau]=h.h_tau + history Gram => one
// block reduction per inner step.
template <int TC, bool LAST>
__global__ void __launch_bounds__(512) refine_kernel(
    const float* __restrict__ b_h, const float* __restrict__ gamma_p,
    const float* __restrict__ beta_p, const float* __restrict__ alpha_p) {
    const int b = blockIdx.x, tid = threadIdx.x;
    const int lane = tid & 31, warp = tid >> 5;
    const int i0 = tid, i1 = tid + 512;

    __shared__ float red[16][18];
    __shared__ float bc[18];     // per-step reduction results
    __shared__ float bc0[18];    // initial reduction (hb.h_tau, sum hb, sum hb^2)
    __shared__ float Gs[16 * 16];
    __shared__ float hsums[16];
    __shared__ float es[16];
    __shared__ float coef[4];    // c1, c2, mu, rstd

    const float g0 = gamma_p[i0], g1 = gamma_p[i1];
    const float be0 = beta_p[i0], be1 = beta_p[i1];

    float hb0 = b_h[i0] + g_zwg[((size_t)TC * BATCH + b) * DH + i0];
    float hb1 = b_h[i1] + g_zwg[((size_t)TC * BATCH + b) * DH + i1];
    if (TC > 0) {
#pragma unroll
        for (int s = 0; s < KSPLIT_H; s++) {
            hb0 += g_parts[s][b * DH + i0];
            hb1 += g_parts[s][b * DH + i1];
        }
    }

    float hv0[TC > 0 ? TC : 1], hv1[TC > 0 ? TC : 1];
#pragma unroll
    for (int tau = 0; tau < TC; tau++) {
        hv0[tau] = g_hist[tau][b * DH + i0];
        hv1[tau] = g_hist[tau][b * DH + i1];
    }

    // load Gram + history sums into smem
    if (TC > 0) {
        if (tid < 256) Gs[tid] = g_gram[b * 256 + tid];
        if (tid < TC)  hsums[tid] = g_hsum[b * 16 + tid];
    }

    // ---- initial reduction: hb.h_tau (TC), sum hb, sum hb^2 ----
    {
        float p[TC + 2];
#pragma unroll
        for (int tau = 0; tau < TC; tau++)
            p[tau] = hv0[tau] * hb0 + hv1[tau] * hb1;
        p[TC]     = hb0 + hb1;
        p[TC + 1] = hb0 * hb0 + hb1 * hb1;
        reduce512<TC + 2>(p, bc0, red);
    }

    float mu = bc0[TC] * (1.f / DH);
    float var = bc0[TC + 1] * (1.f / DH) - mu * mu;
    float rstd = rsqrtf(var + 1e-5f);
    float h0 = fmaxf((hb0 - mu) * rstd * g0 + be0, 0.f);
    float h1 = fmaxf((hb1 - mu) * rstd * g1 + be1, 0.f);

    if (TC > 0) {
        const float alpha = *alpha_p;
        // wd for my lane (used only in warp-0 scalar phase)
        float wdl = 0.f;
        if (warp == 0 && lane < TC)
            wdl = ETA * powf(LAMBDA, (float)(TC - 1 - lane));

#pragma unroll
        for (int s = 0; s < S_STEPS; s++) {
            // one reduction: d[tau]=h.h_tau, plus h.h (skip h.h if LAST)
            {
                float q[TC + (LAST ? 0 : 1)];
#pragma unroll
                for (int tau = 0; tau < TC; tau++)
                    q[tau] = hv0[tau] * h0 + hv1[tau] * h1;
                if (!LAST) q[TC] = h0 * h0 + h1 * h1;
                reduce512<TC + (LAST ? 0 : 1)>(q, bc, red);
            }

            // warp-0 scalar phase
            if (warp == 0) {
                float d = (lane < TC) ? bc[lane] : 0.f;
                float e = wdl * d;
                if (lane < 16) es[lane] = e;
                __syncwarp();
                // Gram matvec f[lane] = sum_sg es[sg]*G[lane][sg]
                // GUARDED: Gs has 256 floats; lanes >= 16 must not touch it.
                float f = 0.f;
                if (lane < TC) {
#pragma unroll
                    for (int sg = 0; sg < TC; sg++)
                        f += es[sg] * Gs[lane * 16 + sg];
                }
                float hbd = (lane < TC) ? bc0[lane] : 0.f;
                float hsm = (lane < TC) ? hsums[lane] : 0.f;
                float pA = e * d;    // -> h.Ah
                float pB = e * hbd;  // -> hb.Ah
                float pC = e * hsm;  // -> sum(Ah)
                float pD = e * f;    // -> Ah.Ah
#pragma unroll
                for (int o = 8; o > 0; o >>= 1) {
                    pA += __shfl_down_sync(0xffffffffu, pA, o);
                    pB += __shfl_down_sync(0xffffffffu, pB, o);
                    pC += __shfl_down_sync(0xffffffffu, pC, o);
                    pD += __shfl_down_sync(0xffffffffu, pD, o);
                }
                if (lane == 0) {
                    float c1, c2;
                    if (!LAST) {
                        float hh = bc[TC];
                        float n1 = sqrtf(hh) + 1e-6f;
                        float n2 = sqrtf(fmaxf(pD, 0.f)) + 1e-6f;
                        float R  = pA / (n1 * n2 + 1e-6f);
                        float Rp = fminf(fmaxf(R, 0.f), 1.f);
                        float spp = fmaxf(alpha, 0.f) + log1pf(expf(-fabsf(alpha)));
                        float spn = fmaxf(-alpha, 0.f) + log1pf(expf(-fabsf(alpha)));
                        float kco = (alpha >= 0.f) ? (1.f + spp) : (1.f / (1.f + spn));
                        float a   = 1.f - powf(1.f - Rp, kco);
                        c1 = 1.f - a * a;
                        c2 = a;
                    } else {
                        c1 = 1.f;
                        c2 = 1.f;
                    }
                    float sum_hn  = c1 * bc0[TC] + c2 * pC;
                    float sum_hn2 = c1 * c1 * bc0[TC + 1] + 2.f * c1 * c2 * pB +
                                    c2 * c2 * pD;
                    float mu_n  = sum_hn * (1.f / DH);
                    float var_n = sum_hn2 * (1.f / DH) - mu_n * mu_n;
                    coef[0] = c1;
                    coef[1] = c2;
                    coef[2] = mu_n;
                    coef[3] = rsqrtf(var_n + 1e-5f);
                }
            }
            __syncthreads();

            // elementwise update
            float Ah0 = 0.f, Ah1 = 0.f;
#pragma unroll
            for (int tau = 0; tau < TC; tau++) {
                Ah0 += es[tau] * hv0[tau];
                Ah1 += es[tau] * hv1[tau];
            }
            const float c1 = coef[0], c2 = coef[1], mun = coef[2], rsn = coef[3];
            float hn0 = c1 * hb0 + c2 * Ah0;
            float hn1 = c1 * hb1 + c2 * Ah1;
            h0 = fmaxf((hn0 - mun) * rsn * g0 + be0, 0.f);
            h1 = fmaxf((hn1 - mun) * rsn * g1 + be1, 0.f);
            __syncthreads();
        }
    }

    g_h[b * DH + i0] = h0;
    g_h[b * DH + i1] = h1;

    if (!LAST) {
        // append h to history: Gram row/col TC, sums
        float r[TC + 2];
#pragma unroll
        for (int tau = 0; tau < TC; tau++)
            r[tau] = hv0[tau] * h0 + hv1[tau] * h1;
        r[TC]     = h0 + h1;
        r[TC + 1] = h0 * h0 + h1 * h1;
        reduce512<TC + 2>(r, bc, red);
        if (tid < TC) {
            g_gram[b * 256 + TC * 16 + tid] = bc[tid];
            g_gram[b * 256 + tid * 16 + TC] = bc[tid];
        }
        if (tid == 511) {
            g_gram[b * 256 + TC * 16 + TC] = bc[TC + 1];
            g_hsum[b * 16 + TC] = bc[TC];
        }
        g_hist[TC][b * DH + i0] = h0;
        g_hist[TC][b * DH + i1] = h1;
    }
}

// ---------------- head loss / acc ----------------
__global__ void __launch_bounds__(512) head_loss_kernel(
    const float* __restrict__ clean, const float* __restrict__ head_b) {
    const int b = blockIdx.x, o = threadIdx.x;
    __shared__ float red[16][18];
    __shared__ float bc[18];
    float pred = head_b[o];
#pragma unroll
    for (int s = 0; s < KSPLIT_O; s++) pred += g_hp[s][b * DOUT + o];
    float c = clean[b * DOUT + o];
    float d = pred - c;
    float v[4] = {pred * c, pred * pred, c * c, d * d};
    reduce512<4>(v, bc, red);
    if (o == 0) {
        g_lossb[b] = bc[3] / (bc[2] + 1e-6f);
        g_accb[b]  = bc[0] / ((sqrtf(bc[1]) + 1e-6f) * (sqrtf(bc[2]) + 1e-6f));
    }
}

__global__ void finalize_kernel(float* __restrict__ out) {
    const int lane = threadIdx.x;
    float l = g_lossb[lane] + g_lossb[lane + 32];
    float a = g_accb[lane] + g_accb[lane + 32];
#pragma unroll
    for (int o = 16; o > 0; o >>= 1) {
        l += __shfl_down_sync(0xffffffffu, l, o);
        a += __shfl_down_sync(0xffffffffu, a, o);
    }
    if (lane == 0) {
        out[0] = l * (1.f / BATCH);
        out[1] = a * (1.f / BATCH);
    }
}

// ---------------- launch -------------------------------------------------
template <int TC>
static void launch_refine(const float* b_h, const float* g, const float* be,
                          const float* al) {
    refine_kernel<TC, (TC == T_STEPS - 1)><<<64, 512>>>(b_h, g, be, al);
}

extern "C" void kernel_launch(void* const* d_in, const int* in_sizes, int n_in,
                              void* d_out, int out_size) {
    const float* z_seq  = (const float*)d_in[0];
    const float* clean  = (const float*)d_in[1];
    const float* W_h    = (const float*)d_in[2];
    const float* W_g    = (const float*)d_in[3];
    const float* b_h    = (const float*)d_in[4];
    const float* ln_g   = (const float*)d_in[5];
    const float* ln_b   = (const float*)d_in[6];
    const float* alpha  = (const float*)d_in[7];
    const float* head_W = (const float*)d_in[8];
    const float* head_b = (const float*)d_in[9];
    float* out = (float*)d_out;

    zwg_kernel<<<dim3(16, 16), 256>>>(z_seq, W_g);

    launch_refine<0>(b_h, ln_g, ln_b, alpha);
    for (int t = 1; t < T_STEPS; t++) {
        wh_step_kernel<<<dim3(16, KSPLIT_H), 256>>>(W_h);
        switch (t) {
            case 1:  launch_refine<1>(b_h, ln_g, ln_b, alpha); break;
            case 2:  launch_refine<2>(b_h, ln_g, ln_b, alpha); break;
            case 3:  launch_refine<3>(b_h, ln_g, ln_b, alpha); break;
            case 4:  launch_refine<4>(b_h, ln_g, ln_b, alpha); break;
            case 5:  launch_refine<5>(b_h, ln_g, ln_b, alpha); break;
            case 6:  launch_refine<6>(b_h, ln_g, ln_b, alpha); break;
            case 7:  launch_refine<7>(b_h, ln_g, ln_b, alpha); break;
            case 8:  launch_refine<8>(b_h, ln_g, ln_b, alpha); break;
            case 9:  launch_refine<9>(b_h, ln_g, ln_b, alpha); break;
            case 10: launch_refine<10>(b_h, ln_g, ln_b, alpha); break;
            case 11: launch_refine<11>(b_h, ln_g, ln_b, alpha); break;
            case 12: launch_refine<12>(b_h, ln_g, ln_b, alpha); break;
            case 13: launch_refine<13>(b_h, ln_g, ln_b, alpha); break;
            case 14: launch_refine<14>(b_h, ln_g, ln_b, alpha); break;
            case 15: launch_refine<15>(b_h, ln_g, ln_b, alpha); break;
        }
    }
    head_gemm_kernel<<<dim3(8, KSPLIT_O), 256>>>(head_W);
    head_loss_kernel<<<64, 512>>>(clean, head_b);
    finalize_kernel<<<1, 32>>>(out);
}

// round 5
// speedup vs baseline: 1.4216x; 1.0129x over previous
#include <cuda_runtime.h>
#include <math.h>

#define T_STEPS 16
#define BATCH   64
#define DG      512
#define DH      1024
#define DOUT    512
#define S_STEPS 3
#define LAMBDA  0.95f
#define ETA     0.5f

#define NBLK 128
#define NTHR 512
#define KSPLIT_H 16
#define KSPLIT_O 16

// ---------------- device scratch ----------------
__device__ float g_h[BATCH * DH];
__device__ float g_parts[KSPLIT_H][BATCH * DH];
__device__ float g_zwg[T_STEPS * BATCH * DH];
__device__ float g_hist[T_STEPS - 1][BATCH * DH];
__device__ float g_gram[BATCH * 16 * 16];
__device__ float g_hsum[BATCH * 16];
__device__ float g_hp[KSPLIT_O][BATCH * DOUT];
__device__ float g_lossb[BATCH];
__device__ float g_accb[BATCH];

// grid barrier state (persists across graph replays; handled by entry-read)
__device__ unsigned g_bar_cnt = 0;
__device__ volatile unsigned g_bar_gen = 0;

__device__ __forceinline__ void bar_sync(unsigned& gen) {
    __syncthreads();
    if (threadIdx.x == 0) {
        __threadfence();
        unsigned t = atomicAdd(&g_bar_cnt, 1u);
        if (t == NBLK - 1) {
            g_bar_cnt = 0u;
            __threadfence();
            g_bar_gen = gen + 1u;
        } else {
            while (g_bar_gen == gen) __nanosleep(32);
        }
    }
    __syncthreads();
    gen++;
}

// ---------------- f32x2 packed FMA ----------------
__device__ __forceinline__ unsigned long long ffma2(unsigned long long a,
                                                    unsigned long long b,
                                                    unsigned long long c) {
    unsigned long long d;
    asm("fma.rn.f32x2 %0, %1, %2, %3;" : "=l"(d) : "l"(a), "l"(b), "l"(c));
    return d;
}
__device__ __forceinline__ void upk2(unsigned long long v, float& x, float& y) {
    asm("mov.b64 {%0,%1}, %2;" : "=f"(x), "=f"(y) : "l"(v));
}

// ---------------- GEMM tile: 64m x 128n, 512 threads --------------------
// out[m][n] = sum_{k in [k0, k0+16*nch)} X[m][k] * W[n][k]
// X: 64-row tile base (ldx), W: 128-row tile base (ldw), out: tile base (ldo).
// thread (mg 0..15, ng 0..31): 4 m-rows x 4 n-cols. X loads bypass L1 (ldcg).
__device__ void gemm_tile(const float* __restrict__ X, int ldx,
                          const float* __restrict__ W, int ldw,
                          float* __restrict__ out, int ldo,
                          int k0, int nch) {
    __shared__ __align__(16) float  Xs[16][68];
    __shared__ __align__(16) float2 Ws[16][132];

    const int tid = threadIdx.x;
    const int mg = tid & 15, ng = tid >> 4;
    const int q  = tid & 3,  rr = tid >> 2;   // rr 0..127

    const float4* Xg = (const float4*)(X + (size_t)rr * ldx + k0) + q; // rr<64 valid
    const float4* Wg = (const float4*)(W + (size_t)rr * ldw + k0) + q;

    float4 xr = make_float4(0.f, 0.f, 0.f, 0.f);
    if (tid < 256) xr = __ldcg(Xg);
    float4 wr = *Wg;

    unsigned long long acc[2][4];
#pragma unroll
    for (int r = 0; r < 2; r++)
#pragma unroll
        for (int c = 0; c < 4; c++) acc[r][c] = 0ull;

#pragma unroll 1
    for (int ch = 0; ch < nch; ch++) {
        __syncthreads();
        if (tid < 256) {
            Xs[q * 4 + 0][rr] = xr.x;
            Xs[q * 4 + 1][rr] = xr.y;
            Xs[q * 4 + 2][rr] = xr.z;
            Xs[q * 4 + 3][rr] = xr.w;
        }
        Ws[q * 4 + 0][rr] = make_float2(wr.x, wr.x);
        Ws[q * 4 + 1][rr] = make_float2(wr.y, wr.y);
        Ws[q * 4 + 2][rr] = make_float2(wr.z, wr.z);
        Ws[q * 4 + 3][rr] = make_float2(wr.w, wr.w);
        __syncthreads();
        if (ch + 1 < nch) {
            if (tid < 256) xr = __ldcg(Xg + (ch + 1) * 4);
            wr = Wg[(ch + 1) * 4];
        }
#pragma unroll
        for (int kk = 0; kk < 16; kk++) {
            ulonglong2 xa = *(const ulonglong2*)&Xs[kk][mg * 4];
            ulonglong2 w0 = *(const ulonglong2*)&Ws[kk][ng * 4];
            ulonglong2 w1 = *(const ulonglong2*)&Ws[kk][ng * 4 + 2];
            acc[0][0] = ffma2(xa.x, w0.x, acc[0][0]);
            acc[1][0] = ffma2(xa.y, w0.x, acc[1][0]);
            acc[0][1] = ffma2(xa.x, w0.y, acc[0][1]);
            acc[1][1] = ffma2(xa.y, w0.y, acc[1][1]);
            acc[0][2] = ffma2(xa.x, w1.x, acc[0][2]);
            acc[1][2] = ffma2(xa.y, w1.x, acc[1][2]);
            acc[0][3] = ffma2(xa.x, w1.y, acc[0][3]);
            acc[1][3] = ffma2(xa.y, w1.y, acc[1][3]);
        }
    }

#pragma unroll
    for (int c = 0; c < 4; c++) {
        const int n = ng * 4 + c;
        float v0, v1;
        upk2(acc[0][c], v0, v1);
        out[(size_t)(mg * 4 + 0) * ldo + n] = v0;
        out[(size_t)(mg * 4 + 1) * ldo + n] = v1;
        upk2(acc[1][c], v0, v1);
        out[(size_t)(mg * 4 + 2) * ldo + n] = v0;
        out[(size_t)(mg * 4 + 3) * ldo + n] = v1;
    }
}

// ---------------- 512-thread multi-value block reduction ----------------
template <int NV>
__device__ __forceinline__ void reduce512(const float* v, float* bc, float (*red)[18]) {
    const int lane = threadIdx.x & 31, warp = threadIdx.x >> 5;
#pragma unroll
    for (int x = 0; x < NV; x++) {
        float s = v[x];
#pragma unroll
        for (int o = 16; o > 0; o >>= 1) s += __shfl_down_sync(0xffffffffu, s, o);
        if (lane == 0) red[warp][x] = s;
    }
    __syncthreads();
#pragma unroll
    for (int x = warp; x < NV; x += 16) {
        float s = (lane < 16) ? red[lane][x] : 0.f;
#pragma unroll
        for (int o = 8; o > 0; o >>= 1) s += __shfl_down_sync(0xffffffffu, s, o);
        if (lane == 0) bc[x] = s;
    }
    __syncthreads();
}

// ---------------- refine phase (blocks 0..63; block = batch b) ----------
// Fixed-15 unrolls; slots >= t are neutralized by wd=0 (stale data * 0 = 0,
// all stale values finite). Exact vs reference.
__device__ void refine_phase(int b, int t, bool last,
                             const float* __restrict__ b_h,
                             const float* __restrict__ gam,
                             const float* __restrict__ bet,
                             const float* __restrict__ alp) {
    const int tid = threadIdx.x, lane = tid & 31, warp = tid >> 5;
    const int i0 = tid, i1 = tid + 512;

    __shared__ float red[16][18];
    __shared__ float bcS[18];
    __shared__ float bc0[18];
    __shared__ float Gs[256];
    __shared__ float hsums[16];
    __shared__ float es[16];
    __shared__ float coef[4];

    const float g0 = gam[i0], g1 = gam[i1];
    const float be0 = bet[i0], be1 = bet[i1];

    float hb0 = b_h[i0] + __ldcg(&g_zwg[((size_t)t * BATCH + b) * DH + i0]);
    float hb1 = b_h[i1] + __ldcg(&g_zwg[((size_t)t * BATCH + b) * DH + i1]);
    if (t > 0) {
#pragma unroll
        for (int s = 0; s < KSPLIT_H; s++) {
            hb0 += __ldcg(&g_parts[s][b * DH + i0]);
            hb1 += __ldcg(&g_parts[s][b * DH + i1]);
        }
    }

    float hv0[15], hv1[15];
#pragma unroll
    for (int tau = 0; tau < 15; tau++) {
        hv0[tau] = g_hist[tau][b * DH + i0];   // same-block producer (persistent)
        hv1[tau] = g_hist[tau][b * DH + i1];
    }

    if (tid < 256) Gs[tid] = g_gram[b * 256 + tid];
    if (tid < 16)  hsums[tid] = g_hsum[b * 16 + tid];

    // initial reduction: hb.h_tau (15), sum hb, sum hb^2
    {
        float p[17];
#pragma unroll
        for (int tau = 0; tau < 15; tau++)
            p[tau] = hv0[tau] * hb0 + hv1[tau] * hb1;
        p[15] = hb0 + hb1;
        p[16] = hb0 * hb0 + hb1 * hb1;
        reduce512<17>(p, bc0, red);
    }

    float mu = bc0[15] * (1.f / DH);
    float var = bc0[16] * (1.f / DH) - mu * mu;
    float rstd = rsqrtf(var + 1e-5f);
    float h0 = fmaxf((hb0 - mu) * rstd * g0 + be0, 0.f);
    float h1 = fmaxf((hb1 - mu) * rstd * g1 + be1, 0.f);

    const float alpha = *alp;
    float wdl = 0.f;
    if (warp == 0 && lane < t)
        wdl = ETA * powf(LAMBDA, (float)(t - 1 - lane));

#pragma unroll
    for (int s = 0; s < S_STEPS; s++) {
        // one reduction: d[tau]=h.h_tau (15) + h.h
        {
            float qv[16];
#pragma unroll
            for (int tau = 0; tau < 15; tau++)
                qv[tau] = hv0[tau] * h0 + hv1[tau] * h1;
            qv[15] = h0 * h0 + h1 * h1;
            reduce512<16>(qv, bcS, red);
        }

        if (warp == 0) {
            float d = (lane < 16) ? bcS[lane] : 0.f;
            float e = wdl * d;                       // 0 for lane >= t
            if (lane < 16) es[lane] = e;
            __syncwarp();
            float f = 0.f;
            if (lane < 16) {
#pragma unroll
                for (int sg = 0; sg < 15; sg++)
                    f += es[sg] * Gs[lane * 16 + sg];
            }
            float hbd = (lane < 16) ? bc0[lane] : 0.f;
            float hsm = (lane < 16) ? hsums[lane] : 0.f;
            float pA = e * d;
            float pB = e * hbd;
            float pC = e * hsm;
            float pD = e * f;
#pragma unroll
            for (int o = 8; o > 0; o >>= 1) {
                pA += __shfl_down_sync(0xffffffffu, pA, o);
                pB += __shfl_down_sync(0xffffffffu, pB, o);
                pC += __shfl_down_sync(0xffffffffu, pC, o);
                pD += __shfl_down_sync(0xffffffffu, pD, o);
            }
            if (lane == 0) {
                float c1, c2;
                if (!last) {
                    float hh = bcS[15];
                    float n1 = sqrtf(hh) + 1e-6f;
                    float n2 = sqrtf(fmaxf(pD, 0.f)) + 1e-6f;
                    float R  = pA / (n1 * n2 + 1e-6f);
                    float Rp = fminf(fmaxf(R, 0.f), 1.f);
                    float spp = fmaxf(alpha, 0.f) + log1pf(expf(-fabsf(alpha)));
                    float spn = fmaxf(-alpha, 0.f) + log1pf(expf(-fabsf(alpha)));
                    float kco = (alpha >= 0.f) ? (1.f + spp) : (1.f / (1.f + spn));
                    float a   = 1.f - powf(1.f - Rp, kco);
                    c1 = 1.f - a * a;
                    c2 = a;
                } else {
                    c1 = 1.f;
                    c2 = 1.f;
                }
                float sum_hn  = c1 * bc0[15] + c2 * pC;
                float sum_hn2 = c1 * c1 * bc0[16] + 2.f * c1 * c2 * pB +
                                c2 * c2 * pD;
                float mu_n  = sum_hn * (1.f / DH);
                float var_n = sum_hn2 * (1.f / DH) - mu_n * mu_n;
                coef[0] = c1;
                coef[1] = c2;
                coef[2] = mu_n;
                coef[3] = rsqrtf(var_n + 1e-5f);
            }
        }
        __syncthreads();

        float Ah0 = 0.f, Ah1 = 0.f;
#pragma unroll
        for (int tau = 0; tau < 15; tau++) {
            Ah0 += es[tau] * hv0[tau];
            Ah1 += es[tau] * hv1[tau];
        }
        const float c1 = coef[0], c2 = coef[1], mun = coef[2], rsn = coef[3];
        float hn0 = c1 * hb0 + c2 * Ah0;
        float hn1 = c1 * hb1 + c2 * Ah1;
        h0 = fmaxf((hn0 - mun) * rsn * g0 + be0, 0.f);
        h1 = fmaxf((hn1 - mun) * rsn * g1 + be1, 0.f);
        __syncthreads();
    }

    g_h[b * DH + i0] = h0;
    g_h[b * DH + i1] = h1;

    if (!last) {
        float r[17];
#pragma unroll
        for (int tau = 0; tau < 15; tau++)
            r[tau] = hv0[tau] * h0 + hv1[tau] * h1;
        r[15] = h0 + h1;
        r[16] = h0 * h0 + h1 * h1;
        reduce512<17>(r, bcS, red);
        if (tid < t) {
            g_gram[b * 256 + t * 16 + tid] = bcS[tid];
            g_gram[b * 256 + tid * 16 + t] = bcS[tid];
        }
        if (tid == 0) {
            g_gram[b * 256 + t * 16 + t] = bcS[16];
            g_hsum[b * 16 + t] = bcS[15];
        }
        g_hist[t][b * DH + i0] = h0;
        g_hist[t][b * DH + i1] = h1;
    }
}

// ---------------- loss phase (blocks 0..63) ----------------
__device__ void loss_phase(int b, const float* __restrict__ clean,
                           const float* __restrict__ head_b) {
    const int o = threadIdx.x;   // DOUT = 512 = NTHR
    __shared__ float red[16][18];
    __shared__ float bc[18];
    float pred = head_b[o];
#pragma unroll
    for (int s = 0; s < KSPLIT_O; s++) pred += __ldcg(&g_hp[s][b * DOUT + o]);
    float c = clean[b * DOUT + o];
    float d = pred - c;
    float v[4] = {pred * c, pred * pred, c * c, d * d};
    reduce512<4>(v, bc, red);
    if (o == 0) {
        g_lossb[b] = bc[3] / (bc[2] + 1e-6f);
        g_accb[b]  = bc[0] / ((sqrtf(bc[1]) + 1e-6f) * (sqrtf(bc[2]) + 1e-6f));
    }
}

// ---------------- the one persistent kernel ----------------
__global__ void __launch_bounds__(NTHR, 1) fused_kernel(
    const float* __restrict__ z_seq, const float* __restrict__ clean,
    const float* __restrict__ W_h, const float* __restrict__ W_g,
    const float* __restrict__ b_h, const float* __restrict__ ln_g,
    const float* __restrict__ ln_b, const float* __restrict__ alpha,
    const float* __restrict__ head_W, const float* __restrict__ head_b,
    float* __restrict__ out) {
    unsigned gen = g_bar_gen;       // survive graph replays
    const int bi = blockIdx.x;

    // phase 0: zwg = z @ W_g^T for all 16 timesteps (1024x1024x512)
    {
        const int mt = bi >> 3, nt = bi & 7;        // 16 m-tiles x 8 n-tiles
        gemm_tile(z_seq + (size_t)mt * 64 * DG, DG,
                  W_g + (size_t)nt * 128 * DG, DG,
                  g_zwg + (size_t)mt * 64 * DH + nt * 128, DH, 0, 32);
    }
    bar_sync(gen);

    for (int t = 0; t < T_STEPS; t++) {
        if (t > 0) {
            const int nt = bi & 7, ks = bi >> 3;    // 8 n-tiles x 16 k-splits
            gemm_tile(g_h, DH,
                      W_h + (size_t)nt * 128 * DH, DH,
                      g_parts[ks] + nt * 128, DH, ks * 64, 4);
            bar_sync(gen);
        }
        if (bi < BATCH)
            refine_phase(bi, t, t == T_STEPS - 1, b_h, ln_g, ln_b, alpha);
        bar_sync(gen);
    }

    // head GEMM: 4 n-tiles x 16 k-splits = 64 blocks
    if (bi < 64) {
        const int nt = bi & 3, ks = bi >> 2;
        gemm_tile(g_h, DH,
                  head_W + (size_t)nt * 128 * DH, DH,
                  g_hp[ks] + nt * 128, DOUT, ks * 64, 4);
    }
    bar_sync(gen);

    if (bi < BATCH) loss_phase(bi, clean, head_b);
    bar_sync(gen);

    if (bi == 0 && threadIdx.x < 32) {
        const int lane = threadIdx.x;
        float l = g_lossb[lane] + g_lossb[lane + 32];
        float a = g_accb[lane] + g_accb[lane + 32];
#pragma unroll
        for (int o = 16; o > 0; o >>= 1) {
            l += __shfl_down_sync(0xffffffffu, l, o);
            a += __shfl_down_sync(0xffffffffu, a, o);
        }
        if (lane == 0) {
            out[0] = l * (1.f / BATCH);
            out[1] = a * (1.f / BATCH);
        }
    }
}

// ---------------- launch ----------------
extern "C" void kernel_launch(void* const* d_in, const int* in_sizes, int n_in,
                              void* d_out, int out_size) {
    const float* z_seq  = (const float*)d_in[0];
    const float* clean  = (const float*)d_in[1];
    const float* W_h    = (const float*)d_in[2];
    const float* W_g    = (const float*)d_in[3];
    const float* b_h    = (const float*)d_in[4];
    const float* ln_g   = (const float*)d_in[5];
    const float* ln_b   = (const float*)d_in[6];
    const float* alpha  = (const float*)d_in[7];
    const float* head_W = (const float*)d_in[8];
    const float* head_b = (const float*)d_in[9];
    float* out = (float*)d_out;

    fused_kernel<<<NBLK, NTHR>>>(z_seq, clean, W_h, W_g, b_h, ln_g, ln_b,
                                 alpha, head_W, head_b, out);
}